// round 1
// baseline (speedup 1.0000x reference)
#include <cuda_runtime.h>
#include <math.h>
#include <stdint.h>

#define MROWS  16384
#define LSEQ   4096
#define BSZ    4
#define DIMC   384
#define DINNER 768
#define DSTATE 16
#define DTRANK 24

// ---------------- scratch (device globals; allocation-free) ----------------
__device__ float g_Wr_t  [768*384];    // reduce_W^T   (K=768, N=384)
__device__ float g_Win_t [384*1536];   // in_proj_W^T
__device__ float g_Winb_t[384*768];
__device__ float g_Winc_t[384*768];
__device__ float g_Wxp_t [768*40];
__device__ float g_Wxpc_t[768*16];
__device__ float g_Wdt_t [24*768];
__device__ float g_Wout_t[768*384];

__device__ float g_concat[MROWS*768];
__device__ float g_msn   [MROWS*384];
__device__ float g_pann  [MROWS*384];
__device__ float g_red   [MROWS*384];
__device__ float g_conn  [MROWS*384];
__device__ float g_xz    [(size_t)MROWS*1536];
__device__ float g_xbp   [MROWS*768];
__device__ float g_xcp   [MROWS*768];
__device__ float g_x     [MROWS*768];
__device__ float g_xb    [MROWS*768];
__device__ float g_xc    [MROWS*768];
__device__ float g_dbl   [MROWS*40];
__device__ float g_dt    [MROWS*768];
__device__ float g_cm    [MROWS*16];
__device__ float g_y     [MROWS*768];
__device__ float g_gf    [MROWS*384];
__device__ float g_img   [MROWS*384];

// ---------------- helpers ----------------
__device__ __forceinline__ float silu_f(float v) {
    return v / (1.f + __expf(-v));
}

// ---------------- weight transpose: out[k*N+n] = in[n*K+k] ----------------
__global__ void wt_transpose(const float* __restrict__ in, float* __restrict__ out,
                             int N, int K) {
    int idx = blockIdx.x * blockDim.x + threadIdx.x;
    if (idx >= N * K) return;
    int n = idx % N;
    int k = idx / N;
    out[(size_t)k * N + n] = in[(size_t)n * K + k];
}

// ---------------- concat copy (float4) ----------------
__global__ void concat_copy(const float4* __restrict__ ms, const float4* __restrict__ pan,
                            float4* __restrict__ out) {
    int idx = blockIdx.x * blockDim.x + threadIdx.x;
    const int per_row = 768 / 4;  // 192
    if (idx >= MROWS * per_row) return;
    int m = idx / per_row;
    int c4 = idx % per_row;
    float4 v;
    if (c4 < 96) v = ms[(size_t)m * 96 + c4];
    else         v = pan[(size_t)m * 96 + (c4 - 96)];
    out[idx] = v;
}

// ---------------- layernorm over 384, one block (128 thr) per row ----------------
__global__ __launch_bounds__(128) void ln_kernel(const float* __restrict__ x,
                                                 const float* __restrict__ w,
                                                 const float* __restrict__ b,
                                                 float* __restrict__ out) {
    int m = blockIdx.x;
    int t = threadIdx.x;
    const float* row = x + (size_t)m * 384;
    float v0 = row[t], v1 = row[t + 128], v2 = row[t + 256];
    float s = v0 + v1 + v2;
    __shared__ float red1[4], red2[4];
    #pragma unroll
    for (int o = 16; o; o >>= 1) s += __shfl_xor_sync(0xffffffffu, s, o);
    if ((t & 31) == 0) red1[t >> 5] = s;
    __syncthreads();
    float mu = (red1[0] + red1[1] + red1[2] + red1[3]) * (1.f / 384.f);
    float d0 = v0 - mu, d1 = v1 - mu, d2 = v2 - mu;
    float q = d0 * d0 + d1 * d1 + d2 * d2;
    #pragma unroll
    for (int o = 16; o; o >>= 1) q += __shfl_xor_sync(0xffffffffu, q, o);
    if ((t & 31) == 0) red2[t >> 5] = q;
    __syncthreads();
    float var = (red2[0] + red2[1] + red2[2] + red2[3]) * (1.f / 384.f);
    float inv = rsqrtf(var + 1e-5f);
    float* o = out + (size_t)m * 384;
    o[t]       = d0 * inv * w[t]       + b[t];
    o[t + 128] = d1 * inv * w[t + 128] + b[t + 128];
    o[t + 256] = d2 * inv * w[t + 256] + b[t + 256];
}

// ---------------- SGEMM: C[M,N] = A[M,K](lda) * Bt[K,N] (+bias,+act,+resid) ----------------
// 128x128 tile, BK=8, 256 threads, 8x8 per thread.
__global__ __launch_bounds__(256) void sgemm(
    const float* __restrict__ A, int lda,
    const float* __restrict__ Bt,
    const float* __restrict__ bias,
    const float* __restrict__ resid, int ldr,
    float* __restrict__ C, int ldc,
    int M, int N, int K, int act)
{
    __shared__ float As[8][132];
    __shared__ float Bs[8][128];
    int tid = threadIdx.x;
    int bm = blockIdx.y * 128, bn = blockIdx.x * 128;
    int row = tid / 16, col = tid % 16;

    float acc[8][8];
    #pragma unroll
    for (int i = 0; i < 8; i++)
        #pragma unroll
        for (int j = 0; j < 8; j++) acc[i][j] = 0.f;

    int a_m = tid / 2;
    int a_k = (tid % 2) * 4;
    int b_n = (tid % 32) * 4;
    int b_k = tid / 32;

    int ktiles = (K + 7) / 8;
    for (int t = 0; t < ktiles; ++t) {
        int k0 = t * 8;
        // A tile -> transposed smem
        {
            float4 av = make_float4(0.f, 0.f, 0.f, 0.f);
            int gm = bm + a_m, gk = k0 + a_k;
            const float* ap = A + (size_t)gm * lda;
            if (gk + 3 < K) {
                av = *(const float4*)(ap + gk);
            } else {
                if (gk + 0 < K) av.x = ap[gk + 0];
                if (gk + 1 < K) av.y = ap[gk + 1];
                if (gk + 2 < K) av.z = ap[gk + 2];
                if (gk + 3 < K) av.w = ap[gk + 3];
            }
            As[a_k + 0][a_m] = av.x;
            As[a_k + 1][a_m] = av.y;
            As[a_k + 2][a_m] = av.z;
            As[a_k + 3][a_m] = av.w;
        }
        // B tile
        {
            float4 bv = make_float4(0.f, 0.f, 0.f, 0.f);
            int gn = bn + b_n, gk = k0 + b_k;
            if (gk < K) {
                const float* bp = Bt + (size_t)gk * N;
                if (gn + 3 < N) {
                    bv = *(const float4*)(bp + gn);
                } else {
                    if (gn + 0 < N) bv.x = bp[gn + 0];
                    if (gn + 1 < N) bv.y = bp[gn + 1];
                    if (gn + 2 < N) bv.z = bp[gn + 2];
                    if (gn + 3 < N) bv.w = bp[gn + 3];
                }
            }
            *(float4*)&Bs[b_k][b_n] = bv;
        }
        __syncthreads();
        #pragma unroll
        for (int k = 0; k < 8; ++k) {
            float a[8], b[8];
            *(float4*)(a)     = *(const float4*)&As[k][row * 8];
            *(float4*)(a + 4) = *(const float4*)&As[k][row * 8 + 4];
            *(float4*)(b)     = *(const float4*)&Bs[k][col * 8];
            *(float4*)(b + 4) = *(const float4*)&Bs[k][col * 8 + 4];
            #pragma unroll
            for (int i = 0; i < 8; i++)
                #pragma unroll
                for (int j = 0; j < 8; j++)
                    acc[i][j] = fmaf(a[i], b[j], acc[i][j]);
        }
        __syncthreads();
    }
    // epilogue
    #pragma unroll
    for (int i = 0; i < 8; i++) {
        int m = bm + row * 8 + i;
        if (m >= M) continue;
        #pragma unroll
        for (int j = 0; j < 8; j++) {
            int n = bn + col * 8 + j;
            if (n >= N) continue;
            float v = acc[i][j];
            if (bias) v += bias[n];
            if (act == 1) {  // softplus
                v = (v > 20.f) ? v : log1pf(expf(v));
            }
            if (resid) v += resid[(size_t)m * ldr + n];
            C[(size_t)m * ldc + n] = v;
        }
    }
}

// ---------------- causal depthwise conv1d (K=4) + SiLU ----------------
__global__ void dwconv1d_silu(const float* __restrict__ x, int xstride,
                              const float* __restrict__ w,
                              const float* __restrict__ bias,
                              float* __restrict__ out) {
    int idx = blockIdx.x * blockDim.x + threadIdx.x;
    if (idx >= MROWS * DINNER) return;
    int d = idx % DINNER;
    int m = idx / DINNER;
    int l = m & (LSEQ - 1);
    float acc = bias[d];
    #pragma unroll
    for (int k = 0; k < 4; k++) {
        int ll = l - 3 + k;
        if (ll >= 0)
            acc += w[d * 4 + k] * x[(size_t)(m + (ll - l)) * xstride + d];
    }
    out[(size_t)m * DINNER + d] = silu_f(acc);
}

// ---------------- selective scan ----------------
// 256 threads = 16 channels x 16 states; grid = BSZ * (768/16) = 192
__global__ __launch_bounds__(256) void scan_kernel(
    const float* __restrict__ u,     // (M,768)
    const float* __restrict__ dt,    // (M,768)
    const float* __restrict__ dbl,   // (M,40), B at offset 24
    const float* __restrict__ Cm,    // (M,16)
    const float* __restrict__ A_log, // (768,16)
    const float* __restrict__ Dp,    // (768,)
    float* __restrict__ y)           // (M,768)
{
    int b  = blockIdx.x / 48;
    int d0 = (blockIdx.x % 48) * 16;
    int tid = threadIdx.x;
    int dl = tid / 16;
    int n  = tid % 16;
    int d = d0 + dl;
    float a = -expf(A_log[d * 16 + n]);
    float Dv = Dp[d];
    __shared__ float sdt[16][16], su[16][16], sB[16][17], sC[16][17];
    float h = 0.f;
    size_t base = (size_t)b * LSEQ;
    int lo = tid / 16, c = tid % 16;  // cooperative load mapping
    for (int l0 = 0; l0 < LSEQ; l0 += 16) {
        size_t m = base + l0 + lo;
        sdt[lo][c] = dt[m * 768 + d0 + c];
        su [lo][c] = u [m * 768 + d0 + c];
        sB [lo][c] = dbl[m * 40 + 24 + c];
        sC [lo][c] = Cm [m * 16 + c];
        __syncthreads();
        #pragma unroll
        for (int s = 0; s < 16; ++s) {
            float dtv = sdt[s][dl];
            float uv  = su [s][dl];
            float Bv  = sB [s][n];
            float Cv  = sC [s][n];
            h = expf(dtv * a) * h + dtv * uv * Bv;
            float p = h * Cv;
            p += __shfl_xor_sync(0xffffffffu, p, 8);
            p += __shfl_xor_sync(0xffffffffu, p, 4);
            p += __shfl_xor_sync(0xffffffffu, p, 2);
            p += __shfl_xor_sync(0xffffffffu, p, 1);
            if (n == 0) y[(base + l0 + s) * 768 + d] = p + uv * Dv;
        }
        __syncthreads();
    }
}

// ---------------- gate: y *= silu(z)  (z = xz[:,768:]) in place ----------------
__global__ void gate_kernel(float* __restrict__ y, const float* __restrict__ xz) {
    int idx = blockIdx.x * blockDim.x + threadIdx.x;
    if (idx >= MROWS * DINNER) return;
    int d = idx % DINNER;
    int m = idx / DINNER;
    float z = xz[(size_t)m * 1536 + 768 + d];
    y[idx] = y[idx] * silu_f(z);
}

// ---------------- (B,L,C) -> (B,C,L) transpose ----------------
__global__ void transpose_LC(const float* __restrict__ in, float* __restrict__ out) {
    __shared__ float t[32][33];
    int bb = blockIdx.z;
    int c0 = blockIdx.x * 32, l0 = blockIdx.y * 32;
    const float* ip = in + (size_t)bb * LSEQ * DIMC;
    float* op = out + (size_t)bb * DIMC * LSEQ;
    int tx = threadIdx.x, ty = threadIdx.y;
    #pragma unroll
    for (int i = 0; i < 32; i += 8)
        t[ty + i][tx] = ip[(size_t)(l0 + ty + i) * DIMC + c0 + tx];
    __syncthreads();
    #pragma unroll
    for (int i = 0; i < 32; i += 8)
        op[(size_t)(c0 + ty + i) * LSEQ + l0 + tx] = t[tx][ty + i];
}

// ---------------- final 3x3 depthwise conv (SAME) on (B,C,64,64) ----------------
__global__ void dwconv3x3(const float* __restrict__ img, const float* __restrict__ w,
                          const float* __restrict__ bias, float* __restrict__ out) {
    int idx = blockIdx.x * blockDim.x + threadIdx.x;
    if (idx >= BSZ * DIMC * 64 * 64) return;
    int wv = idx & 63;
    int h  = (idx >> 6) & 63;
    int c  = (idx >> 12) % DIMC;
    int b  = idx / (DIMC * 4096);
    const float* ip = img + ((size_t)b * DIMC + c) * 4096;
    const float* wc = w + c * 9;
    float acc = bias[c];
    #pragma unroll
    for (int dh = -1; dh <= 1; dh++) {
        int hh = h + dh;
        if (hh < 0 || hh >= 64) continue;
        #pragma unroll
        for (int dw = -1; dw <= 1; dw++) {
            int ww = wv + dw;
            if (ww < 0 || ww >= 64) continue;
            acc += wc[(dh + 1) * 3 + (dw + 1)] * ip[hh * 64 + ww];
        }
    }
    out[idx] = acc;
}

// ---------------- host ----------------
static void launch_gemm(const float* A, int lda, const float* Bt,
                        const float* bias, const float* resid, int ldr,
                        float* C, int ldc, int M, int N, int K, int act) {
    dim3 grid((N + 127) / 128, (M + 127) / 128);
    sgemm<<<grid, 256>>>(A, lda, Bt, bias, resid, ldr, C, ldc, M, N, K, act);
}

extern "C" void kernel_launch(void* const* d_in, const int* in_sizes, int n_in,
                              void* d_out, int out_size) {
    const float* ms          = (const float*)d_in[0];
    const float* pan         = (const float*)d_in[1];
    const float* reduce_W    = (const float*)d_in[2];
    const float* reduce_b    = (const float*)d_in[3];
    const float* ln1_w       = (const float*)d_in[4];
    const float* ln1_b       = (const float*)d_in[5];
    const float* ln2_w       = (const float*)d_in[6];
    const float* ln2_b       = (const float*)d_in[7];
    const float* ln3_w       = (const float*)d_in[8];
    const float* ln3_b       = (const float*)d_in[9];
    const float* in_proj_W   = (const float*)d_in[10];
    const float* in_proj_b_W = (const float*)d_in[11];
    const float* in_proj_c_W = (const float*)d_in[12];
    const float* conv_w      = (const float*)d_in[13];
    const float* conv_bias   = (const float*)d_in[14];
    const float* conv_b_w    = (const float*)d_in[15];
    const float* conv_b_bias = (const float*)d_in[16];
    const float* conv_c_w    = (const float*)d_in[17];
    const float* conv_c_bias = (const float*)d_in[18];
    const float* x_proj_W    = (const float*)d_in[19];
    const float* x_proj_c_W  = (const float*)d_in[20];
    const float* dt_proj_W   = (const float*)d_in[21];
    const float* dt_proj_bias= (const float*)d_in[22];
    const float* A_log       = (const float*)d_in[23];
    const float* Dvec        = (const float*)d_in[24];
    const float* out_proj_W  = (const float*)d_in[25];
    const float* dwconv_w    = (const float*)d_in[26];
    const float* dwconv_b    = (const float*)d_in[27];
    float* out = (float*)d_out;

    float *pWr, *pWin, *pWinb, *pWinc, *pWxp, *pWxpc, *pWdt, *pWout;
    float *pconcat, *pmsn, *ppann, *pred, *pconn, *pxz, *pxbp, *pxcp;
    float *px, *pxb, *pxc, *pdbl, *pdt, *pcm, *py, *pgf, *pimg;
    cudaGetSymbolAddress((void**)&pWr,   g_Wr_t);
    cudaGetSymbolAddress((void**)&pWin,  g_Win_t);
    cudaGetSymbolAddress((void**)&pWinb, g_Winb_t);
    cudaGetSymbolAddress((void**)&pWinc, g_Winc_t);
    cudaGetSymbolAddress((void**)&pWxp,  g_Wxp_t);
    cudaGetSymbolAddress((void**)&pWxpc, g_Wxpc_t);
    cudaGetSymbolAddress((void**)&pWdt,  g_Wdt_t);
    cudaGetSymbolAddress((void**)&pWout, g_Wout_t);
    cudaGetSymbolAddress((void**)&pconcat, g_concat);
    cudaGetSymbolAddress((void**)&pmsn,  g_msn);
    cudaGetSymbolAddress((void**)&ppann, g_pann);
    cudaGetSymbolAddress((void**)&pred,  g_red);
    cudaGetSymbolAddress((void**)&pconn, g_conn);
    cudaGetSymbolAddress((void**)&pxz,   g_xz);
    cudaGetSymbolAddress((void**)&pxbp,  g_xbp);
    cudaGetSymbolAddress((void**)&pxcp,  g_xcp);
    cudaGetSymbolAddress((void**)&px,    g_x);
    cudaGetSymbolAddress((void**)&pxb,   g_xb);
    cudaGetSymbolAddress((void**)&pxc,   g_xc);
    cudaGetSymbolAddress((void**)&pdbl,  g_dbl);
    cudaGetSymbolAddress((void**)&pdt,   g_dt);
    cudaGetSymbolAddress((void**)&pcm,   g_cm);
    cudaGetSymbolAddress((void**)&py,    g_y);
    cudaGetSymbolAddress((void**)&pgf,   g_gf);
    cudaGetSymbolAddress((void**)&pimg,  g_img);

    // weight transposes
    auto wt = [](const float* in, float* o, int N, int K) {
        int tot = N * K;
        wt_transpose<<<(tot + 255) / 256, 256>>>(in, o, N, K);
    };
    wt(reduce_W,    pWr,   384, 768);
    wt(in_proj_W,   pWin,  1536, 384);
    wt(in_proj_b_W, pWinb, 768, 384);
    wt(in_proj_c_W, pWinc, 768, 384);
    wt(x_proj_W,    pWxp,  40, 768);
    wt(x_proj_c_W,  pWxpc, 16, 768);
    wt(dt_proj_W,   pWdt,  768, 24);
    wt(out_proj_W,  pWout, 384, 768);

    // concat + reduce GEMM + LNs
    {
        int tot = MROWS * 192;
        concat_copy<<<(tot + 255) / 256, 256>>>((const float4*)ms, (const float4*)pan,
                                                (float4*)pconcat);
    }
    launch_gemm(pconcat, 768, pWr, reduce_b, nullptr, 0, pred, 384,
                MROWS, 384, 768, 0);
    ln_kernel<<<MROWS, 128>>>(ms,   ln1_w, ln1_b, pmsn);
    ln_kernel<<<MROWS, 128>>>(pan,  ln2_w, ln2_b, ppann);
    ln_kernel<<<MROWS, 128>>>(pred, ln3_w, ln3_b, pconn);

    // projections
    launch_gemm(pmsn,  384, pWin,  nullptr, nullptr, 0, pxz,  1536, MROWS, 1536, 384, 0);
    launch_gemm(ppann, 384, pWinb, nullptr, nullptr, 0, pxbp, 768,  MROWS, 768,  384, 0);
    launch_gemm(pconn, 384, pWinc, nullptr, nullptr, 0, pxcp, 768,  MROWS, 768,  384, 0);

    // depthwise causal convs + SiLU
    {
        int tot = MROWS * DINNER;
        int blocks = (tot + 255) / 256;
        dwconv1d_silu<<<blocks, 256>>>(pxz,  1536, conv_w,   conv_bias,   px);
        dwconv1d_silu<<<blocks, 256>>>(pxbp, 768,  conv_b_w, conv_b_bias, pxb);
        dwconv1d_silu<<<blocks, 256>>>(pxcp, 768,  conv_c_w, conv_c_bias, pxc);
    }

    // small projections
    launch_gemm(pxb, 768, pWxp,  nullptr, nullptr, 0, pdbl, 40, MROWS, 40, 768, 0);
    launch_gemm(pxc, 768, pWxpc, nullptr, nullptr, 0, pcm,  16, MROWS, 16, 768, 0);
    launch_gemm(pdbl, 40, pWdt, dt_proj_bias, nullptr, 0, pdt, 768, MROWS, 768, 24, 1);

    // selective scan
    scan_kernel<<<BSZ * 48, 256>>>(px, pdt, pdbl, pcm, A_log, Dvec, py);

    // gate (in place on y)
    {
        int tot = MROWS * DINNER;
        gate_kernel<<<(tot + 255) / 256, 256>>>(py, pxz);
    }

    // out_proj + residual(ms)
    launch_gemm(py, 768, pWout, nullptr, ms, 384, pgf, 384, MROWS, 384, 768, 0);

    // (B,L,C) -> (B,C,HW) transpose, then 3x3 depthwise conv
    {
        dim3 grid(DIMC / 32, LSEQ / 32, BSZ);
        dim3 blk(32, 8);
        transpose_LC<<<grid, blk>>>(pgf, pimg);
    }
    {
        int tot = BSZ * DIMC * 64 * 64;
        dwconv3x3<<<(tot + 255) / 256, 256>>>(pimg, dwconv_w, dwconv_b, out);
    }
}